// round 1
// baseline (speedup 1.0000x reference)
#include <cuda_runtime.h>
#include <math.h>

#define FULL 0xffffffffu

__device__ __forceinline__ float ex2f_(float x){ float r; asm("ex2.approx.ftz.f32 %0, %1;" : "=f"(r):"f"(x)); return r; }
__device__ __forceinline__ float lg2f_(float x){ float r; asm("lg2.approx.ftz.f32 %0, %1;" : "=f"(r):"f"(x)); return r; }

#define B_ 8192
#define T_ 256
#define K_ 16
#define WARPS 8
#define LOG2E 1.4426950408889634f
#define LN2   0.6931471805599453f

__global__ __launch_bounds__(WARPS*32, 4)
void crf_kernel(const float* __restrict__ em, const int* __restrict__ tags,
                const int* __restrict__ w2w, const int* __restrict__ icnt,
                const int* __restrict__ dist, const float* __restrict__ cw,
                const float* __restrict__ trans, const float* __restrict__ start,
                float* __restrict__ out)
{
    // ETT: transposed exp(trans): [m][j][i], row stride 20 floats, m stride 320
    __shared__ __align__(16) float ETT[4*320];
    __shared__ __align__(16) float RAW[4*256];
    __shared__ __align__(16) float PS[WARPS][2][32];

    int tid = threadIdx.x;
    for (int idx = tid; idx < 1024; idx += WARPS*32) {
        int m = idx >> 8, r = (idx >> 4) & 15, c = idx & 15;  // trans[m][r][c]
        float v = trans[idx];
        RAW[idx] = v;
        ETT[m*320 + c*20 + r] = expf(v);
    }
    __syncthreads();

    int warp = tid >> 5;
    int lane = tid & 31;
    int h = lane >> 4;
    int j = lane & 15;
    int seq = (blockIdx.x * WARPS + warp) * 2 + h;

    const float* emb = em   + (size_t)seq * T_ * K_;
    const int*   tg  = tags + (size_t)seq * T_;
    const int*   ww  = w2w  + (size_t)seq * (T_-1);
    const int*   ib  = icnt + (size_t)seq * (T_-1);
    const int*   db  = dist + (size_t)seq * (T_-1);

    float wj = __ldg(&cw[j]);
    float sj = __ldg(&start[j]);

    float e0 = emb[j];
    int prev = tg[0];
    float alpha = (sj + e0) * LOG2E;            // log2-domain alpha
    float gold  = (prev == j) ? wj * (sj + e0) : 0.0f;

    // software-pipelined per-step loads
    int a_  = ww[0], b_ = ib[0], d_ = db[0];
    float e_ = emb[K_ + j];
    int tn_  = tg[1];

    int buf = 0;
    #pragma unroll 1
    for (int t = 0; t < T_-1; ++t) {
        // prefetch next step's inputs
        int tp = (t+1 < T_-1) ? t+1 : t;
        int a2 = ww[tp], b2 = ib[tp], d2 = db[tp];
        float e2 = emb[(tp+1)*K_ + j];
        int tn2  = tg[tp+1];

        int m = (a_ == 1) ? 0 : ((b_ == 0) ? 1 : ((d_ == 0) ? 2 : 3));

        // max over the 16-lane half
        float mx = alpha;
        mx = fmaxf(mx, __shfl_xor_sync(FULL, mx, 8, 16));
        mx = fmaxf(mx, __shfl_xor_sync(FULL, mx, 4, 16));
        mx = fmaxf(mx, __shfl_xor_sync(FULL, mx, 2, 16));
        mx = fmaxf(mx, __shfl_xor_sync(FULL, mx, 1, 16));

        float p = ex2f_(alpha - mx);
        PS[warp][buf][lane] = p;
        __syncwarp();

        const float4* pv = (const float4*)&PS[warp][buf][h*16];
        const float4* ev = (const float4*)&ETT[m*320 + j*20];
        float4 p0 = pv[0], p1 = pv[1], p2 = pv[2], p3 = pv[3];
        float4 q0 = ev[0], q1 = ev[1], q2 = ev[2], q3 = ev[3];

        float s0 = fmaf(p0.x,q0.x, fmaf(p0.y,q0.y, fmaf(p0.z,q0.z, p0.w*q0.w)));
        float s1 = fmaf(p1.x,q1.x, fmaf(p1.y,q1.y, fmaf(p1.z,q1.z, p1.w*q1.w)));
        float s2 = fmaf(p2.x,q2.x, fmaf(p2.y,q2.y, fmaf(p2.z,q2.z, p2.w*q2.w)));
        float s3 = fmaf(p3.x,q3.x, fmaf(p3.y,q3.y, fmaf(p3.z,q3.z, p3.w*q3.w)));
        float sum = (s0 + s1) + (s2 + s3);

        // alpha update (log2 domain): new = mx + log2(sum) + e*log2e
        alpha = fmaf(e_, LOG2E, mx + lg2f_(sum));

        // gold path
        float trg = RAW[m*256 + prev*16 + j];
        if (tn_ == j) gold = fmaf(wj, trg + e_, gold);
        prev = tn_;

        a_ = a2; b_ = b2; d_ = d2; e_ = e2; tn_ = tn2;
        buf ^= 1;
    }

    // log_Z = ln2 * log2sumexp2(alpha)
    float mx = alpha;
    mx = fmaxf(mx, __shfl_xor_sync(FULL, mx, 8, 16));
    mx = fmaxf(mx, __shfl_xor_sync(FULL, mx, 4, 16));
    mx = fmaxf(mx, __shfl_xor_sync(FULL, mx, 2, 16));
    mx = fmaxf(mx, __shfl_xor_sync(FULL, mx, 1, 16));
    float z = ex2f_(alpha - mx);
    z += __shfl_xor_sync(FULL, z, 8, 16);
    z += __shfl_xor_sync(FULL, z, 4, 16);
    z += __shfl_xor_sync(FULL, z, 2, 16);
    z += __shfl_xor_sync(FULL, z, 1, 16);
    float logZ = LN2 * (mx + lg2f_(z));

    float g = gold;
    g += __shfl_xor_sync(FULL, g, 8, 16);
    g += __shfl_xor_sync(FULL, g, 4, 16);
    g += __shfl_xor_sync(FULL, g, 2, 16);
    g += __shfl_xor_sync(FULL, g, 1, 16);

    if (j == 0) {
        out[seq]      = g;
        out[B_ + seq] = logZ;
    }
}

extern "C" void kernel_launch(void* const* d_in, const int* in_sizes, int n_in,
                              void* d_out, int out_size) {
    const float* em    = (const float*)d_in[0];
    const int*   tags  = (const int*)d_in[1];
    const int*   w2w   = (const int*)d_in[2];
    const int*   icnt  = (const int*)d_in[3];
    const int*   dist  = (const int*)d_in[4];
    const float* cw    = (const float*)d_in[5];
    const float* trans = (const float*)d_in[6];
    const float* start = (const float*)d_in[7];
    float* out = (float*)d_out;

    int blocks = B_ / (2 * WARPS);   // 512
    crf_kernel<<<blocks, WARPS*32>>>(em, tags, w2w, icnt, dist, cw, trans, start, out);
}

// round 2
// speedup vs baseline: 2.0004x; 2.0004x over previous
#include <cuda_runtime.h>
#include <cuda_fp16.h>
#include <math.h>

#define FULL 0xffffffffu
#define B_ 8192
#define T_ 256
#define K_ 16
#define LOG2E 1.4426950408889634f
#define LN2   0.6931471805599453f
#define ROWH 24                  // halves per ETT row (48B stride: 16B-aligned, conflict-floor)
#define MSTRIDE (K_*ROWH)        // halves per matrix = 384 (768B)
#define BIAS 6.0f

__device__ unsigned g_codes[B_*T_];   // 8MB scratch: per-step packed {m_off, tag, tr_fp16}; slot 255 = start-gold bits

static __device__ __forceinline__ float ex2f_(float x){ float r; asm("ex2.approx.ftz.f32 %0,%1;":"=f"(r):"f"(x)); return r; }
static __device__ __forceinline__ float lg2f_(float x){ float r; asm("lg2.approx.ftz.f32 %0,%1;":"=f"(r):"f"(x)); return r; }

// ---------- pass 1: pack per-step codes + start-gold ----------
__global__ void pack_kernel(const int* __restrict__ tags, const int* __restrict__ w2w,
                            const int* __restrict__ icnt, const int* __restrict__ dist,
                            const float* __restrict__ cw, const float* __restrict__ trans,
                            const float* __restrict__ start, const float* __restrict__ em)
{
    int b = blockIdx.y;
    int t = blockIdx.x*64 + threadIdx.x;
    if (t < T_-1) {
        int a  = w2w [b*(T_-1)+t];
        int ic = icnt[b*(T_-1)+t];
        int di = dist[b*(T_-1)+t];
        int m = (a==1) ? 0 : ((ic==0) ? 1 : ((di==0) ? 2 : 3));
        int t0 = tags[b*T_+t];
        int t1 = tags[b*T_+t+1];
        float tr = __ldg(&trans[(m*K_+t0)*K_+t1]);
        unsigned hb = (unsigned)__half_as_ushort(__float2half_rn(tr));
        g_codes[b*T_+t] = ((unsigned)(m*MSTRIDE*2) << 20) | ((unsigned)t1 << 16) | hb;
    } else if (t == T_-1) {
        int t0 = tags[b*T_];
        float sg = __ldg(&cw[t0]) * (__ldg(&start[t0]) + em[(size_t)b*(T_*K_) + t0]);
        g_codes[b*T_+t] = __float_as_uint(sg);
    }
}

// ---------- pass 2: serial CRF recursion, lane-per-tag, 2 seqs/warp ----------
#define HC(w) (*reinterpret_cast<const half2*>(&(w)))

__global__ __launch_bounds__(64, 16)
void crf_main(const float* __restrict__ em, const float* __restrict__ cw,
              const float* __restrict__ trans, const float* __restrict__ start,
              float* __restrict__ out)
{
    __shared__ __align__(16) half ETT[4*MSTRIDE];       // exp(trans), transposed, fp16, padded rows
    __shared__ __align__(16) half PS[2][2][32];         // p broadcast buffers (double-buffered)

    int tid = threadIdx.x;
    #pragma unroll
    for (int k = 0; k < 16; ++k) {
        int idx = tid + k*64;                            // trans[m][i][jj]
        int m = idx >> 8, i = (idx >> 4) & 15, jj = idx & 15;
        ETT[m*MSTRIDE + jj*ROWH + i] = __float2half_rn(expf(trans[idx]));
    }
    __syncthreads();

    int warp = tid >> 5, lane = tid & 31, h = lane >> 4, j = lane & 15;
    int seq = (blockIdx.x*2 + warp)*2 + h;

    const float*    pe = em + (size_t)seq*(T_*K_) + j;
    const unsigned* pc = g_codes + seq*T_;

    float wj = __ldg(&cw[j]);
    float e0 = pe[0];
    float alpha = (__ldg(&start[j]) + e0) * LOG2E;      // log2-domain
    float gold = 0.0f;

    // prefetch blocks 0 and 1 (codes + emissions, 4 steps each)
    uint4 cC = *reinterpret_cast<const uint4*>(pc);
    uint4 cN = *reinterpret_cast<const uint4*>(pc + 4);
    float eC0=pe[1*K_], eC1=pe[2*K_], eC2=pe[3*K_], eC3=pe[4*K_];
    float eN0=pe[5*K_], eN1=pe[6*K_], eN2=pe[7*K_], eN3=pe[8*K_];

#define STEP(EV, CV, BUF) do {                                                      \
    unsigned c_ = (CV); float e_ = (EV);                                            \
    float s_  = __shfl_sync(FULL, alpha, 0, 16);                                    \
    float eb_ = fmaf(e_, LOG2E, s_ + BIAS);                                         \
    float x_  = (alpha - s_) - BIAS;                                                \
    float p_  = ex2f_(x_);                                                          \
    PS[warp][BUF][lane] = __float2half_rn(p_);                                      \
    __syncwarp();                                                                   \
    const char* er_ = ((const char*)ETT) + (c_ >> 20) + j*(ROWH*2);                 \
    float4 E0_ = *reinterpret_cast<const float4*>(er_);                             \
    float4 E1_ = *reinterpret_cast<const float4*>(er_ + 16);                        \
    const char* pr_ = (const char*)&PS[warp][BUF][h*16];                            \
    float4 P0_ = *reinterpret_cast<const float4*>(pr_);                             \
    float4 P1_ = *reinterpret_cast<const float4*>(pr_ + 16);                        \
    half2 a0_ = __hmul2(HC(P0_.x), HC(E0_.x));                                      \
    half2 a1_ = __hmul2(HC(P0_.y), HC(E0_.y));                                      \
    a0_ = __hfma2(HC(P0_.z), HC(E0_.z), a0_);                                       \
    a1_ = __hfma2(HC(P0_.w), HC(E0_.w), a1_);                                       \
    a0_ = __hfma2(HC(P1_.x), HC(E1_.x), a0_);                                       \
    a1_ = __hfma2(HC(P1_.y), HC(E1_.y), a1_);                                       \
    a0_ = __hfma2(HC(P1_.z), HC(E1_.z), a0_);                                       \
    a1_ = __hfma2(HC(P1_.w), HC(E1_.w), a1_);                                       \
    a0_ = __hadd2(a0_, a1_);                                                        \
    float2 f_ = __half22float2(a0_);                                                \
    alpha = eb_ + lg2f_(f_.x + f_.y);                                               \
    unsigned tn_ = (c_ >> 16) & 15;                                                 \
    float tr_ = __half2float(__ushort_as_half((unsigned short)(c_ & 0xffffu)));     \
    if ((unsigned)j == tn_) gold = fmaf(wj, tr_ + e_, gold);                        \
} while (0)

    #pragma unroll 1
    for (int blk = 0; blk < 63; ++blk) {
        int nb = blk + 2; if (nb > 63) nb = 63;
        uint4 cP = *reinterpret_cast<const uint4*>(pc + nb*4);
        int r0 = nb*4 + 1;
        float eP0 = pe[min(r0+0,255)*K_];
        float eP1 = pe[min(r0+1,255)*K_];
        float eP2 = pe[min(r0+2,255)*K_];
        float eP3 = pe[min(r0+3,255)*K_];

        STEP(eC0, cC.x, 0);
        STEP(eC1, cC.y, 1);
        STEP(eC2, cC.z, 0);
        STEP(eC3, cC.w, 1);

        cC = cN; cN = cP;
        eC0=eN0; eC1=eN1; eC2=eN2; eC3=eN3;
        eN0=eP0; eN1=eP1; eN2=eP2; eN3=eP3;
    }
    // tail: steps 252..254 (block 63); cC.w carries the start-gold bits
    STEP(eC0, cC.x, 0);
    STEP(eC1, cC.y, 1);
    STEP(eC2, cC.z, 0);
    float sg = __uint_as_float(cC.w);

    // logZ = ln2 * log2sumexp2(alpha) over 16 lanes
    float mx = alpha;
    mx = fmaxf(mx, __shfl_xor_sync(FULL, mx, 8, 16));
    mx = fmaxf(mx, __shfl_xor_sync(FULL, mx, 4, 16));
    mx = fmaxf(mx, __shfl_xor_sync(FULL, mx, 2, 16));
    mx = fmaxf(mx, __shfl_xor_sync(FULL, mx, 1, 16));
    float z = ex2f_(alpha - mx);
    z += __shfl_xor_sync(FULL, z, 8, 16);
    z += __shfl_xor_sync(FULL, z, 4, 16);
    z += __shfl_xor_sync(FULL, z, 2, 16);
    z += __shfl_xor_sync(FULL, z, 1, 16);
    float logZ = LN2 * (mx + lg2f_(z));

    float g = gold;
    g += __shfl_xor_sync(FULL, g, 8, 16);
    g += __shfl_xor_sync(FULL, g, 4, 16);
    g += __shfl_xor_sync(FULL, g, 2, 16);
    g += __shfl_xor_sync(FULL, g, 1, 16);

    if (j == 0) {
        out[seq]      = g + sg;
        out[B_ + seq] = logZ;
    }
}

extern "C" void kernel_launch(void* const* d_in, const int* in_sizes, int n_in,
                              void* d_out, int out_size) {
    const float* em    = (const float*)d_in[0];
    const int*   tags  = (const int*)d_in[1];
    const int*   w2w   = (const int*)d_in[2];
    const int*   icnt  = (const int*)d_in[3];
    const int*   dist  = (const int*)d_in[4];
    const float* cw    = (const float*)d_in[5];
    const float* trans = (const float*)d_in[6];
    const float* start = (const float*)d_in[7];
    float* out = (float*)d_out;

    dim3 pg(4, B_);
    pack_kernel<<<pg, 64>>>(tags, w2w, icnt, dist, cw, trans, start, em);

    int blocks = B_ / 4;   // 2048 blocks, 2 warps each, 2 seqs/warp
    crf_main<<<blocks, 64>>>(em, cw, trans, start, out);
}

// round 3
// speedup vs baseline: 2.0039x; 1.0018x over previous
#include <cuda_runtime.h>
#include <cuda_fp16.h>
#include <math.h>

#define FULL 0xffffffffu
#define B_ 8192
#define T_ 256
#define K_ 16
#define LOG2E 1.4426950408889634f
#define LN2   0.6931471805599453f
#define ROWH 24                  // halves per ETT row (48B stride: 16B-aligned, conflict-floor)
#define MSTRIDE (K_*ROWH)        // halves per matrix = 384 (768B)
#define BIAS 6.0f

__device__ unsigned g_codes[B_*T_];   // 8MB scratch: per-step packed {m_off, tag, tr_fp16}; slot 255 = start-gold bits

static __device__ __forceinline__ float ex2f_(float x){ float r; asm("ex2.approx.ftz.f32 %0,%1;":"=f"(r):"f"(x)); return r; }
static __device__ __forceinline__ float lg2f_(float x){ float r; asm("lg2.approx.ftz.f32 %0,%1;":"=f"(r):"f"(x)); return r; }

// ---------- pass 1: pack per-step codes + start-gold ----------
__global__ void pack_kernel(const int* __restrict__ tags, const int* __restrict__ w2w,
                            const int* __restrict__ icnt, const int* __restrict__ dist,
                            const float* __restrict__ cw, const float* __restrict__ trans,
                            const float* __restrict__ start, const float* __restrict__ em)
{
    int b = blockIdx.y;
    int t = blockIdx.x*64 + threadIdx.x;
    if (t < T_-1) {
        int a  = w2w [b*(T_-1)+t];
        int ic = icnt[b*(T_-1)+t];
        int di = dist[b*(T_-1)+t];
        int m = (a==1) ? 0 : ((ic==0) ? 1 : ((di==0) ? 2 : 3));
        int t0 = tags[b*T_+t];
        int t1 = tags[b*T_+t+1];
        float tr = __ldg(&trans[(m*K_+t0)*K_+t1]);
        unsigned hb = (unsigned)__half_as_ushort(__float2half_rn(tr));
        g_codes[b*T_+t] = ((unsigned)(m*MSTRIDE*2) << 20) | ((unsigned)t1 << 16) | hb;
    } else if (t == T_-1) {
        int t0 = tags[b*T_];
        float sg = __ldg(&cw[t0]) * (__ldg(&start[t0]) + em[(size_t)b*(T_*K_) + t0]);
        g_codes[b*T_+t] = __float_as_uint(sg);
    }
}

// ---------- pass 2: serial CRF recursion, lane-per-tag, 2 seqs/warp ----------
#define HC(w) (*reinterpret_cast<const half2*>(&(w)))

__global__ __launch_bounds__(64, 16)
void crf_main(const float* __restrict__ em, const float* __restrict__ cw,
              const float* __restrict__ trans, const float* __restrict__ start,
              float* __restrict__ out)
{
    __shared__ __align__(16) half ETT[4*MSTRIDE];       // exp(trans), transposed, fp16, padded rows
    __shared__ __align__(16) half PS[2][2][32];         // p broadcast buffers (double-buffered)

    int tid = threadIdx.x;
    #pragma unroll
    for (int k = 0; k < 16; ++k) {
        int idx = tid + k*64;                            // trans[m][i][jj]
        int m = idx >> 8, i = (idx >> 4) & 15, jj = idx & 15;
        ETT[m*MSTRIDE + jj*ROWH + i] = __float2half_rn(expf(trans[idx]));
    }
    __syncthreads();

    int warp = tid >> 5, lane = tid & 31, h = lane >> 4, j = lane & 15;
    int seq = (blockIdx.x*2 + warp)*2 + h;

    const float*    pe = em + (size_t)seq*(T_*K_) + j;
    const unsigned* pc = g_codes + seq*T_;

    float wj = __ldg(&cw[j]);
    float e0 = pe[0];
    float alpha = (__ldg(&start[j]) + e0) * LOG2E;      // log2-domain
    float gold = 0.0f;

    // prefetch blocks 0 and 1 (codes + emissions, 4 steps each)
    uint4 cC = *reinterpret_cast<const uint4*>(pc);
    uint4 cN = *reinterpret_cast<const uint4*>(pc + 4);
    float eC0=pe[1*K_], eC1=pe[2*K_], eC2=pe[3*K_], eC3=pe[4*K_];
    float eN0=pe[5*K_], eN1=pe[6*K_], eN2=pe[7*K_], eN3=pe[8*K_];

#define STEP(EV, CV, BUF) do {                                                      \
    unsigned c_ = (CV); float e_ = (EV);                                            \
    float s_  = __shfl_sync(FULL, alpha, 0, 16);                                    \
    float eb_ = fmaf(e_, LOG2E, s_ + BIAS);                                         \
    float x_  = (alpha - s_) - BIAS;                                                \
    float p_  = ex2f_(x_);                                                          \
    PS[warp][BUF][lane] = __float2half_rn(p_);                                      \
    __syncwarp();                                                                   \
    const char* er_ = ((const char*)ETT) + (c_ >> 20) + j*(ROWH*2);                 \
    float4 E0_ = *reinterpret_cast<const float4*>(er_);                             \
    float4 E1_ = *reinterpret_cast<const float4*>(er_ + 16);                        \
    const char* pr_ = (const char*)&PS[warp][BUF][h*16];                            \
    float4 P0_ = *reinterpret_cast<const float4*>(pr_);                             \
    float4 P1_ = *reinterpret_cast<const float4*>(pr_ + 16);                        \
    half2 a0_ = __hmul2(HC(P0_.x), HC(E0_.x));                                      \
    half2 a1_ = __hmul2(HC(P0_.y), HC(E0_.y));                                      \
    a0_ = __hfma2(HC(P0_.z), HC(E0_.z), a0_);                                       \
    a1_ = __hfma2(HC(P0_.w), HC(E0_.w), a1_);                                       \
    a0_ = __hfma2(HC(P1_.x), HC(E1_.x), a0_);                                       \
    a1_ = __hfma2(HC(P1_.y), HC(E1_.y), a1_);                                       \
    a0_ = __hfma2(HC(P1_.z), HC(E1_.z), a0_);                                       \
    a1_ = __hfma2(HC(P1_.w), HC(E1_.w), a1_);                                       \
    a0_ = __hadd2(a0_, a1_);                                                        \
    float2 f_ = __half22float2(a0_);                                                \
    alpha = eb_ + lg2f_(f_.x + f_.y);                                               \
    unsigned tn_ = (c_ >> 16) & 15;                                                 \
    float tr_ = __half2float(__ushort_as_half((unsigned short)(c_ & 0xffffu)));     \
    if ((unsigned)j == tn_) gold = fmaf(wj, tr_ + e_, gold);                        \
} while (0)

    #pragma unroll 1
    for (int blk = 0; blk < 63; ++blk) {
        int nb = blk + 2; if (nb > 63) nb = 63;
        uint4 cP = *reinterpret_cast<const uint4*>(pc + nb*4);
        int r0 = nb*4 + 1;
        float eP0 = pe[min(r0+0,255)*K_];
        float eP1 = pe[min(r0+1,255)*K_];
        float eP2 = pe[min(r0+2,255)*K_];
        float eP3 = pe[min(r0+3,255)*K_];

        STEP(eC0, cC.x, 0);
        STEP(eC1, cC.y, 1);
        STEP(eC2, cC.z, 0);
        STEP(eC3, cC.w, 1);

        cC = cN; cN = cP;
        eC0=eN0; eC1=eN1; eC2=eN2; eC3=eN3;
        eN0=eP0; eN1=eP1; eN2=eP2; eN3=eP3;
    }
    // tail: steps 252..254 (block 63); cC.w carries the start-gold bits
    STEP(eC0, cC.x, 0);
    STEP(eC1, cC.y, 1);
    STEP(eC2, cC.z, 0);
    float sg = __uint_as_float(cC.w);

    // logZ = ln2 * log2sumexp2(alpha) over 16 lanes
    float mx = alpha;
    mx = fmaxf(mx, __shfl_xor_sync(FULL, mx, 8, 16));
    mx = fmaxf(mx, __shfl_xor_sync(FULL, mx, 4, 16));
    mx = fmaxf(mx, __shfl_xor_sync(FULL, mx, 2, 16));
    mx = fmaxf(mx, __shfl_xor_sync(FULL, mx, 1, 16));
    float z = ex2f_(alpha - mx);
    z += __shfl_xor_sync(FULL, z, 8, 16);
    z += __shfl_xor_sync(FULL, z, 4, 16);
    z += __shfl_xor_sync(FULL, z, 2, 16);
    z += __shfl_xor_sync(FULL, z, 1, 16);
    float logZ = LN2 * (mx + lg2f_(z));

    float g = gold;
    g += __shfl_xor_sync(FULL, g, 8, 16);
    g += __shfl_xor_sync(FULL, g, 4, 16);
    g += __shfl_xor_sync(FULL, g, 2, 16);
    g += __shfl_xor_sync(FULL, g, 1, 16);

    if (j == 0) {
        out[seq]      = g + sg;
        out[B_ + seq] = logZ;
    }
}

extern "C" void kernel_launch(void* const* d_in, const int* in_sizes, int n_in,
                              void* d_out, int out_size) {
    const float* em    = (const float*)d_in[0];
    const int*   tags  = (const int*)d_in[1];
    const int*   w2w   = (const int*)d_in[2];
    const int*   icnt  = (const int*)d_in[3];
    const int*   dist  = (const int*)d_in[4];
    const float* cw    = (const float*)d_in[5];
    const float* trans = (const float*)d_in[6];
    const float* start = (const float*)d_in[7];
    float* out = (float*)d_out;

    dim3 pg(4, B_);
    pack_kernel<<<pg, 64>>>(tags, w2w, icnt, dist, cw, trans, start, em);

    int blocks = B_ / 4;   // 2048 blocks, 2 warps each, 2 seqs/warp
    crf_main<<<blocks, 64>>>(em, cw, trans, start, out);
}

// round 5
// speedup vs baseline: 2.1442x; 1.0700x over previous
#include <cuda_runtime.h>
#include <cuda_fp16.h>
#include <math.h>

#define FULL 0xffffffffu
#define B_ 8192
#define T_ 256
#define K_ 16
#define LOG2E 1.4426950408889634f
#define LN2   0.6931471805599453f

__device__ unsigned g_codes32[B_*64];   // 2MB: 1 byte/step {m:2, t1:4, spare:2}
__device__ float    g_goldtr[B_];       // w[t0]*start[t0] + sum_t w[t1]*tr

static __device__ __forceinline__ float ex2f_(float x){ float r; asm("ex2.approx.ftz.f32 %0,%1;":"=f"(r):"f"(x)); return r; }
static __device__ __forceinline__ float lg2f_(float x){ float r; asm("lg2.approx.ftz.f32 %0,%1;":"=f"(r):"f"(x)); return r; }
static __device__ __forceinline__ __half2 u2h(unsigned u){ return *reinterpret_cast<__half2*>(&u); }

// ---------------- pass 1: pack codes + gold transition part ----------------
__global__ __launch_bounds__(256)
void pack_kernel(const int* __restrict__ tags, const int* __restrict__ w2w,
                 const int* __restrict__ icnt, const int* __restrict__ dist,
                 const float* __restrict__ cw, const float* __restrict__ trans,
                 const float* __restrict__ start)
{
    __shared__ float TR[1024];
    int tid = threadIdx.x;
    for (int i = tid; i < 1024; i += 256) TR[i] = trans[i];
    __syncthreads();

    int wp = tid >> 5, lane = tid & 31;
    int seq = blockIdx.x*8 + wp;
    const int* tg = tags + seq*T_;
    float gsum = 0.f;

    #pragma unroll 1
    for (int c = 0; c < 8; ++c) {
        int t = c*32 + lane;
        unsigned byte;
        if (t < 255) {
            int a  = w2w [seq*(T_-1)+t];
            int ic = icnt[seq*(T_-1)+t];
            int di = dist[seq*(T_-1)+t];
            int m = (a==1) ? 0 : ((ic==0) ? 1 : ((di==0) ? 2 : 3));
            int t0 = tg[t], t1 = tg[t+1];
            gsum += __ldg(&cw[t1]) * TR[(m*16+t0)*16+t1];
            byte = (unsigned)m | ((unsigned)t1 << 2);
            if (t == 0) byte |= ((unsigned)tg[0] & 3u) << 6;
            if (t == 1) byte |= (((unsigned)tg[0] >> 2) & 3u) << 6;
        } else {                       // t == 255: start-score gold part
            int t0 = tg[0];
            gsum += __ldg(&cw[t0]) * __ldg(&start[t0]);
            byte = 0;
        }
        unsigned v = byte << ((lane & 3)*8);
        v |= __shfl_xor_sync(FULL, v, 1);
        v |= __shfl_xor_sync(FULL, v, 2);
        if ((lane & 3) == 0)
            g_codes32[seq*64 + c*8 + (lane >> 2)] = v;
    }
    gsum += __shfl_xor_sync(FULL, gsum, 16);
    gsum += __shfl_xor_sync(FULL, gsum, 8);
    gsum += __shfl_xor_sync(FULL, gsum, 4);
    gsum += __shfl_xor_sync(FULL, gsum, 2);
    gsum += __shfl_xor_sync(FULL, gsum, 1);
    if (lane == 0) g_goldtr[seq] = gsum;
}

// ---------------- pass 2: linear-domain CRF, lane-per-tag, 2 seqs/warp ----------------
__global__ __launch_bounds__(64)
void crf_main(const float* __restrict__ em, const float* __restrict__ cw,
              const float* __restrict__ trans, const float* __restrict__ start,
              float* __restrict__ out)
{
    __shared__ __align__(16) __half ETT[4*384];   // exp(trans)^T, 48B column stride
    __shared__ __align__(16) __half PS[2][2][32];

    int tid = threadIdx.x;
    #pragma unroll
    for (int k = 0; k < 16; ++k) {
        int idx = tid + k*64;                      // trans[m][i][jj]
        int m = idx >> 8, i = (idx >> 4) & 15, jj = idx & 15;
        ETT[m*384 + jj*24 + i] = __float2half_rn(expf(trans[idx]));
    }
    __syncthreads();

    int warp = tid >> 5, lane = tid & 31, h = lane >> 4, j = lane & 15;
    int seq = (blockIdx.x*2 + warp)*2 + h;

    const float* pe = em + (size_t)seq*(T_*K_) + j;
    const uint4* pc4 = reinterpret_cast<const uint4*>(g_codes32 + seq*64);
    unsigned ett_sh = (unsigned)__cvta_generic_to_shared(ETT);
    unsigned jcol = ett_sh + (unsigned)(j*48);

    uint4 E0a = *reinterpret_cast<const uint4*>(reinterpret_cast<const char*>(ETT) + j*48);
    uint4 E0b = *reinterpret_cast<const uint4*>(reinterpret_cast<const char*>(ETT) + j*48 + 16);

    float wj = __ldg(&cw[j]);
    float e0 = pe[0];

    uint4 cC = pc4[0], cN = pc4[1];
    int t0 = (int)((cC.x >> 6) & 3u) | ((int)((cC.x >> 14) & 3u) << 2);

    float a    = ex2f_((__ldg(&start[j]) + e0) * LOG2E);   // linear domain
    float gold = (j == t0) ? wj * e0 : 0.f;
    int ksum = 0;

    float eb[8];
    #pragma unroll
    for (int r = 0; r < 8; ++r) eb[r] = pe[(r+1)*K_];

    // Rescale math: k = E0(lane0) - 127.  sc = 2^(-k-6)  (exponent field 248-E0,
    // constant 0x7C000000).  ksum += k+6 = E0 - 121.  p = a*sc is exact power-of-2
    // scaling; the 2^-6 bias keeps the fp16 broadcast overflow-safe.
#define STEP(W, SH, SIDX, RI, BF) do {                                          \
    unsigned b_ = ((W) >> (SH)) & 0xffu;                                        \
    float e_ = eb[RI];                                                          \
    eb[RI] = pe[min((SIDX)+9, 255)*K_];                                         \
    float ee_ = ex2f_(e_ * LOG2E);                                              \
    float s_ = __shfl_sync(FULL, a, 0, 16);                                     \
    unsigned bi_ = __float_as_uint(s_);                                         \
    ksum += (int)(bi_ >> 23) - 121;                                             \
    float sc_ = __uint_as_float(0x7C000000u - (bi_ & 0x7f800000u));             \
    PS[warp][BF][lane] = __float2half_rn(a * sc_);                              \
    __syncwarp();                                                               \
    unsigned m_ = b_ & 3u;                                                      \
    unsigned ea_ = jcol + m_*768u;                                              \
    uint4 Ra_ = E0a, Rb_ = E0b;                                                 \
    asm volatile("{\n\t.reg .pred p;\n\tsetp.ne.u32 p, %8, 0;\n\t"              \
      "@p ld.shared.v4.b32 {%0,%1,%2,%3}, [%9];\n\t"                            \
      "@p ld.shared.v4.b32 {%4,%5,%6,%7}, [%10];\n\t}"                          \
      : "+r"(Ra_.x),"+r"(Ra_.y),"+r"(Ra_.z),"+r"(Ra_.w),                        \
        "+r"(Rb_.x),"+r"(Rb_.y),"+r"(Rb_.z),"+r"(Rb_.w)                         \
      : "r"(m_), "r"(ea_), "r"(ea_+16u));                                       \
    const uint4* pv_ = reinterpret_cast<const uint4*>(&PS[warp][BF][h*16]);     \
    uint4 P0_ = pv_[0], P1_ = pv_[1];                                           \
    __half2 x0_ = __hmul2(u2h(P0_.x), u2h(Ra_.x));                              \
    __half2 x1_ = __hmul2(u2h(P0_.y), u2h(Ra_.y));                              \
    x0_ = __hfma2(u2h(P0_.z), u2h(Ra_.z), x0_);                                 \
    x1_ = __hfma2(u2h(P0_.w), u2h(Ra_.w), x1_);                                 \
    x0_ = __hfma2(u2h(P1_.x), u2h(Rb_.x), x0_);                                 \
    x1_ = __hfma2(u2h(P1_.y), u2h(Rb_.y), x1_);                                 \
    x0_ = __hfma2(u2h(P1_.z), u2h(Rb_.z), x0_);                                 \
    x1_ = __hfma2(u2h(P1_.w), u2h(Rb_.w), x1_);                                 \
    x0_ = __hadd2(x0_, x1_);                                                    \
    float2 f2_ = __half22float2(x0_);                                           \
    a = (f2_.x + f2_.y) * ee_;                                                  \
    unsigned t1_ = (b_ >> 2) & 15u;                                             \
    if ((unsigned)j == t1_) gold = fmaf(wj, e_, gold);                          \
} while (0)

    #pragma unroll 1
    for (int chunk = 0; chunk < 16; ++chunk) {
        int base = chunk*16;
        unsigned w0 = cC.x, w1 = cC.y, w2 = cC.z, w3 = cC.w;
        STEP(w0,  0, base+ 0, 0, 0);
        STEP(w0,  8, base+ 1, 1, 1);
        STEP(w0, 16, base+ 2, 2, 0);
        STEP(w0, 24, base+ 3, 3, 1);
        STEP(w1,  0, base+ 4, 4, 0);
        STEP(w1,  8, base+ 5, 5, 1);
        STEP(w1, 16, base+ 6, 6, 0);
        STEP(w1, 24, base+ 7, 7, 1);
        STEP(w2,  0, base+ 8, 0, 0);
        STEP(w2,  8, base+ 9, 1, 1);
        STEP(w2, 16, base+10, 2, 0);
        STEP(w2, 24, base+11, 3, 1);
        STEP(w3,  0, base+12, 4, 0);
        STEP(w3,  8, base+13, 5, 1);
        STEP(w3, 16, base+14, 6, 0);
        if (chunk < 15) { STEP(w3, 24, base+15, 7, 1); }
        cC = cN; cN = pc4[min(chunk+2, 15)];
    }
#undef STEP

    // logZ = ln2 * (log2(sum_j a_j) + ksum)
    float s = a;
    s += __shfl_xor_sync(FULL, s, 8, 16);
    s += __shfl_xor_sync(FULL, s, 4, 16);
    s += __shfl_xor_sync(FULL, s, 2, 16);
    s += __shfl_xor_sync(FULL, s, 1, 16);
    float logZ = LN2 * (lg2f_(s) + (float)ksum);

    float g = gold;
    g += __shfl_xor_sync(FULL, g, 8, 16);
    g += __shfl_xor_sync(FULL, g, 4, 16);
    g += __shfl_xor_sync(FULL, g, 2, 16);
    g += __shfl_xor_sync(FULL, g, 1, 16);

    if (j == 0) {
        out[seq]      = g + g_goldtr[seq];
        out[B_ + seq] = logZ;
    }
}

extern "C" void kernel_launch(void* const* d_in, const int* in_sizes, int n_in,
                              void* d_out, int out_size) {
    const float* em    = (const float*)d_in[0];
    const int*   tags  = (const int*)d_in[1];
    const int*   w2w   = (const int*)d_in[2];
    const int*   icnt  = (const int*)d_in[3];
    const int*   dist  = (const int*)d_in[4];
    const float* cw    = (const float*)d_in[5];
    const float* trans = (const float*)d_in[6];
    const float* start = (const float*)d_in[7];
    float* out = (float*)d_out;

    pack_kernel<<<B_/8, 256>>>(tags, w2w, icnt, dist, cw, trans, start);
    crf_main<<<B_/4, 64>>>(em, cw, trans, start, out);
}